// round 15
// baseline (speedup 1.0000x reference)
#include <cuda_runtime.h>
#include <cuda_fp16.h>
#include <stdint.h>
#include <math.h>

namespace {
constexpr int H = 128, NNODE = 13, NJN = 12, OBS_LEN = 141, NLAYER = 3;
constexpr int GPT = 9;               // graphs per CTA -> 117 rows, padded to 128
constexpr int MROWS = 128;
constexpr int NTHREADS = 1024;       // 32 warps: 4 M-slices x 8 N-slices
constexpr int BASE_F = 33, JOINT_F = 9;

constexpr uint32_t PITCHB = 272;     // fp16 row: 128 elems + 8 pad (conflict-free ld/stmatrix)
constexpr uint32_t MATB   = MROWS * PITCHB;        // 34816

constexpr uint32_t OFF_XH  = 0;              // X fp16 (all layers; decoder reads fp16)
constexpr uint32_t OFF_Z1  = MATB;           // Z1 fp16 (single plane)
constexpr uint32_t OFF_W1  = 2 * MATB;       // W_rel fp16
constexpr uint32_t OFF_W2  = 3 * MATB;       // W_root fp16
constexpr uint32_t OFF_OBS = 4 * MATB;
constexpr uint32_t OFF_BIAS = OFF_OBS + GPT * 144 * 4;
constexpr uint32_t BO_BEB = 0, BO_BEJ = 512, BO_BREL = 1024, BO_WDEC = 2560, BO_BDEC = 3072;
constexpr uint32_t OFF_WEB = OFF_Z1;         // encoder weights (pre-layer0, in Z1 area)
constexpr uint32_t OFF_WEJ = OFF_Z1 + 16896;
constexpr uint32_t SMEM_DYN = OFF_BIAS + 3104;     // ~144 KB

__device__ __constant__ int8_t NSRC[13] = {4,2,2,1,2,2,1,2,2,1,2,2,1};
__device__ __constant__ int8_t SRCS[13][4] = {
    {1,4,7,10},{0,2,0,0},{1,3,0,0},{2,0,0,0},{0,5,0,0},{4,6,0,0},{5,0,0,0},
    {0,8,0,0},{7,9,0,0},{8,0,0,0},{0,11,0,0},{10,12,0,0},{11,0,0,0}};
__device__ __constant__ int8_t BIDX[11] = {0,1,2,3,4,5,6,7,8,45,46};

__device__ __half g_wh[NLAYER][2][H * H];    // fp16 weights [layer][rel/root][n*128+k]

__device__ __forceinline__ uint32_t smem_u32(const void* p) {
    uint32_t a;
    asm("{ .reg .u64 t; cvta.to.shared.u64 t, %1; cvt.u32.u64 %0, t; }" : "=r"(a) : "l"(p));
    return a;
}
__device__ __forceinline__ float elu1(float v) { return v > 0.f ? v : __expf(v) - 1.f; }

__device__ __forceinline__ void ldsm4(uint32_t& r0, uint32_t& r1, uint32_t& r2, uint32_t& r3,
                                      uint32_t addr) {
    asm volatile("ldmatrix.sync.aligned.m8n8.x4.shared.b16 {%0,%1,%2,%3}, [%4];"
                 : "=r"(r0), "=r"(r1), "=r"(r2), "=r"(r3) : "r"(addr));
}
__device__ __forceinline__ void stsm4(uint32_t addr, uint32_t r0, uint32_t r1,
                                      uint32_t r2, uint32_t r3) {
    asm volatile("stmatrix.sync.aligned.m8n8.x4.shared.b16 [%0], {%1,%2,%3,%4};"
                 :: "r"(addr), "r"(r0), "r"(r1), "r"(r2), "r"(r3) : "memory");
}
__device__ __forceinline__ void mma16816(float* c, const uint32_t* a, uint32_t b0, uint32_t b1) {
    asm volatile(
        "mma.sync.aligned.m16n8k16.row.col.f32.f16.f16.f32 "
        "{%0,%1,%2,%3}, {%4,%5,%6,%7}, {%8,%9}, {%0,%1,%2,%3};"
        : "+f"(c[0]), "+f"(c[1]), "+f"(c[2]), "+f"(c[3])
        : "r"(a[0]), "r"(a[1]), "r"(a[2]), "r"(a[3]), "r"(b0), "r"(b1));
}

// packed f32x2 -> f16x2 (low half = first arg; PTX puts first source in HIGH half)
__device__ __forceinline__ uint32_t cvtpack(float lo, float hi) {
    uint32_t r;
    asm("cvt.rn.f16x2.f32 %0, %1, %2;" : "=r"(r) : "f"(hi), "f"(lo));
    return r;
}
__device__ __forceinline__ void store8h(char* sm, uint32_t doff, const float* v) {
    uint4 hh;
    uint32_t* ph = (uint32_t*)&hh;
#pragma unroll
    for (int k = 0; k < 4; k++) ph[k] = cvtpack(v[2 * k], v[2 * k + 1]);
    *(uint4*)(sm + OFF_XH + doff) = hh;
}
} // namespace

__global__ void conv_weights_kernel(const float* __restrict__ W_rel,
                                    const float* __restrict__ W_root) {
    int i = blockIdx.x * blockDim.x + threadIdx.x;
    if (i >= NLAYER * 2 * H * H) return;
    int l = i / (2 * H * H);
    int r = i % (2 * H * H);
    int g = r / (H * H);
    int e = r % (H * H);
    float w = (g == 0) ? W_rel[l * H * H + e] : W_root[l * H * H + e];
    g_wh[l][g][e] = __float2half_rn(w);
}

__global__ __launch_bounds__(NTHREADS, 1) void gnn_mma_kernel(
    const float* __restrict__ obs,
    const float* __restrict__ We_b, const float* __restrict__ be_b,
    const float* __restrict__ We_j, const float* __restrict__ be_j,
    const float* __restrict__ b_rel,
    const float* __restrict__ W_dec, const float* __restrict__ b_dec,
    float* __restrict__ out, int B)
{
    extern __shared__ char sm[];
    const uint32_t sb = smem_u32(sm);
    const int tid = threadIdx.x, lane = tid & 31, wid = tid >> 5;
    const int m0 = (wid >> 3) * 32;          // 32-row slice (4 slices)
    const int n0 = (wid & 7) * 16;           // 16-col slice (8 slices)
    const int g0 = blockIdx.x * GPT;
    const int ng = min(GPT, B - g0);
    const int rows_real = ng * NNODE;

    // ---- stage biases / encoder weights / obs ----
    if (tid < H) {
        ((float*)(sm + OFF_BIAS + BO_BEB))[tid]  = be_b[tid];
        ((float*)(sm + OFF_BIAS + BO_BEJ))[tid]  = be_j[tid];
        ((float*)(sm + OFF_BIAS + BO_WDEC))[tid] = W_dec[tid];
    }
    if (tid >= H && tid < H + NLAYER * H)
        ((float*)(sm + OFF_BIAS + BO_BREL))[tid - H] = b_rel[tid - H];
    if (tid == 0) ((float*)(sm + OFF_BIAS + BO_BDEC))[0] = b_dec[0];
    for (int i = tid; i < H * BASE_F; i += NTHREADS) {
        int h = i / BASE_F, f = i - h * BASE_F;
        ((float*)(sm + OFF_WEB))[f * H + h] = We_b[i];
    }
    for (int i = tid; i < H * JOINT_F; i += NTHREADS) {
        int h = i / JOINT_F, f = i - h * JOINT_F;
        ((float*)(sm + OFF_WEJ))[f * H + h] = We_j[i];
    }
    for (int i = tid; i < ng * OBS_LEN; i += NTHREADS) {
        int g = i / OBS_LEN, k = i - g * OBS_LEN;
        ((float*)(sm + OFF_OBS))[g * 144 + k] = obs[(size_t)(g0 + g) * OBS_LEN + k];
    }
    __syncthreads();

    // ---- phase A: encoder (X fp16) + stage W(0) concurrently ----
    {
        const uint4* rel = (const uint4*)&g_wh[0][0][0];
        const uint4* roo = (const uint4*)&g_wh[0][1][0];
        for (int idx = tid; idx < H * 16; idx += NTHREADS) {
            uint32_t d = (uint32_t)(idx >> 4) * PITCHB + (uint32_t)(idx & 15) * 16;
            *(uint4*)(sm + OFF_W1 + d) = rel[idx];
            *(uint4*)(sm + OFF_W2 + d) = roo[idx];
        }
    }
    for (int idx = tid; idx < MROWS * 16; idx += NTHREADS) {
        int row = idx >> 4, c0 = (idx & 15) << 3;
        uint32_t doff = (uint32_t)row * PITCHB + (uint32_t)c0 * 2;
        if (row >= rows_real) {
            *(uint4*)(sm + OFF_XH + doff) = make_uint4(0, 0, 0, 0);  // zero pads ONCE
            continue;
        }
        int g = row / NNODE, n = row - g * NNODE;
        const float* ob = (const float*)(sm + OFF_OBS) + g * 144;
        float acc[8];
        if (n == 0) {
            const float* be = (const float*)(sm + OFF_BIAS + BO_BEB);
#pragma unroll
            for (int e = 0; e < 8; e++) acc[e] = be[c0 + e];
#pragma unroll
            for (int t = 0; t < 3; t++)
#pragma unroll
                for (int i2 = 0; i2 < 11; i2++) {
                    float ft = ob[t * 47 + BIDX[i2]];
                    const float* w = (const float*)(sm + OFF_WEB) + (t * 11 + i2) * H + c0;
#pragma unroll
                    for (int e = 0; e < 8; e++) acc[e] = fmaf(ft, w[e], acc[e]);
                }
        } else {
            int j = n - 1;
            const float* be = (const float*)(sm + OFF_BIAS + BO_BEJ);
#pragma unroll
            for (int e = 0; e < 8; e++) acc[e] = be[c0 + e];
#pragma unroll
            for (int f = 0; f < 9; f++) {
                float ft = ob[(f / 3) * 47 + 9 + (f % 3) * 12 + j];
                const float* w = (const float*)(sm + OFF_WEJ) + f * H + c0;
#pragma unroll
                for (int e = 0; e < 8; e++) acc[e] = fmaf(ft, w[e], acc[e]);
            }
        }
#pragma unroll
        for (int e = 0; e < 8; e++) acc[e] = elu1(acc[e]);
        store8h(sm, doff, acc);
    }

    // ---- layers:  x' = elu( S·(X@Wrel^T) + X@Wroot^T + b ) ----
    const int cb = n0 + 2 * (lane & 3);      // fragment col base for this thread
    for (int l = 0; l < NLAYER; l++) {
        __syncthreads();  // X(l)+W(l) ready; prev epilogue's Z1 reads done

        // acc1 = X@W1^T (-> Z1 spill); acc2 = bias + X@W2^T (register-resident)
        float acc1[2][2][4], acc2[2][2][4];   // [mt][ns][4]
        {
            const float* brl = (const float*)(sm + OFF_BIAS + BO_BREL) + l * H;
#pragma unroll
            for (int mt = 0; mt < 2; mt++)
#pragma unroll
                for (int ns = 0; ns < 2; ns++) {
                    const float b0 = brl[cb + ns * 8];
                    const float b1 = brl[cb + ns * 8 + 1];
                    acc1[mt][ns][0] = 0.f; acc1[mt][ns][1] = 0.f;
                    acc1[mt][ns][2] = 0.f; acc1[mt][ns][3] = 0.f;
                    acc2[mt][ns][0] = b0;  acc2[mt][ns][1] = b1;
                    acc2[mt][ns][2] = b0;  acc2[mt][ns][3] = b1;
                }
        }
        {
            const uint32_t arow = (uint32_t)(lane & 15);
            const uint32_t acol = (uint32_t)((lane >> 4) << 4);
            const uint32_t brow = (uint32_t)((lane & 7) + ((lane >> 4) << 3));
            const uint32_t bcol = (uint32_t)(((lane >> 3) & 1) << 4);
            const uint32_t aH0 = sb + OFF_XH + ((uint32_t)m0 + arow) * PITCHB + acol;
            const uint32_t bro = ((uint32_t)n0 + brow) * PITCHB + bcol;
            const uint32_t b10 = sb + OFF_W1 + bro;
            const uint32_t b20 = sb + OFF_W2 + bro;
#pragma unroll 2
            for (int k = 0; k < 8; k++) {
                const uint32_t kb = (uint32_t)k * 32u;
                uint32_t ah[2][4];
                ldsm4(ah[0][0], ah[0][1], ah[0][2], ah[0][3], aH0 + kb);
                ldsm4(ah[1][0], ah[1][1], ah[1][2], ah[1][3], aH0 + 16u * PITCHB + kb);
                uint32_t w0, w1, w2, w3;
                ldsm4(w0, w1, w2, w3, b10 + kb);
#pragma unroll
                for (int mt = 0; mt < 2; mt++) {
                    mma16816(acc1[mt][0], ah[mt], w0, w1);
                    mma16816(acc1[mt][1], ah[mt], w2, w3);
                }
                ldsm4(w0, w1, w2, w3, b20 + kb);
#pragma unroll
                for (int mt = 0; mt < 2; mt++) {
                    mma16816(acc2[mt][0], ah[mt], w0, w1);
                    mma16816(acc2[mt][1], ah[mt], w2, w3);
                }
            }
        }

        // coalesced Z1 spill via stmatrix (fp16)
        {
            const uint32_t t = (uint32_t)lane >> 3;          // tile 0..3
            const uint32_t srow = (uint32_t)m0 + ((t >> 1) << 3) + (lane & 7);
            const uint32_t scol = (uint32_t)n0 + (t & 1) * 8;
            const uint32_t boff = srow * PITCHB + scol * 2;
#pragma unroll
            for (int mt = 0; mt < 2; mt++) {
                stsm4(sb + OFF_Z1 + boff + (uint32_t)mt * (16u * PITCHB),
                      cvtpack(acc1[mt][0][0], acc1[mt][0][1]),
                      cvtpack(acc1[mt][1][0], acc1[mt][1][1]),
                      cvtpack(acc1[mt][0][2], acc1[mt][0][3]),
                      cvtpack(acc1[mt][1][2], acc1[mt][1][3]));
            }
        }
        __syncthreads();  // Z1 visible; all GEMM X reads done -> XH writable

        // fragment-mapped epilogue: x' = elu( acc2 + S·Z1 ) -> X fp16
        // (u32 accesses in fragment mapping are bank-conflict-free; pads skipped)
#pragma unroll
        for (int mt = 0; mt < 2; mt++)
#pragma unroll
            for (int half = 0; half < 2; half++) {
                const int r = m0 + mt * 16 + half * 8 + (lane >> 2);
                if (r >= rows_real) continue;
                const int gb = (r / NNODE) * NNODE;
                const int n  = r - gb;
                const int cnt = NSRC[n];
#pragma unroll
                for (int ns = 0; ns < 2; ns++) {
                    const int col = cb + ns * 8;
                    float v0 = acc2[mt][ns][2 * half];
                    float v1 = acc2[mt][ns][2 * half + 1];
                    for (int k2 = 0; k2 < cnt; k2++) {
                        uint32_t u = *(const uint32_t*)(sm + OFF_Z1 +
                            (uint32_t)(gb + SRCS[n][k2]) * PITCHB + (uint32_t)col * 2);
                        float2 f = __half22float2(*reinterpret_cast<__half2*>(&u));
                        v0 += f.x;
                        v1 += f.y;
                    }
                    *(uint32_t*)(sm + OFF_XH + (uint32_t)r * PITCHB + (uint32_t)col * 2) =
                        cvtpack(elu1(v0), elu1(v1));
                }
            }

        // stage W(l+1) in the same phase (W buffers idle during epilogue)
        if (l + 1 < NLAYER) {
            const uint4* rel = (const uint4*)&g_wh[l + 1][0][0];
            const uint4* roo = (const uint4*)&g_wh[l + 1][1][0];
            for (int idx = tid; idx < H * 16; idx += NTHREADS) {
                uint32_t d = (uint32_t)(idx >> 4) * PITCHB + (uint32_t)(idx & 15) * 16;
                *(uint4*)(sm + OFF_W1 + d) = rel[idx];
                *(uint4*)(sm + OFF_W2 + d) = roo[idx];
            }
        }
    }
    __syncthreads();

    // ---- decoder (final X fp16 at OFF_XH) ----
    if (tid < ng * NJN) {
        int g = tid / NJN, j = tid - g * NJN;
        const char* xrow = sm + OFF_XH + (uint32_t)(g * NNODE + 1 + j) * PITCHB;
        const float* wd = (const float*)(sm + OFF_BIAS + BO_WDEC);
        float acc = ((const float*)(sm + OFF_BIAS + BO_BDEC))[0];
#pragma unroll
        for (int c = 0; c < H; c += 8) {
            uint4 p = *(const uint4*)(xrow + c * 2);
            const uint32_t* w32 = (const uint32_t*)&p;
#pragma unroll
            for (int k = 0; k < 4; k++) {
                float2 f = __half22float2(*reinterpret_cast<const __half2*>(&w32[k]));
                acc = fmaf(f.x, wd[c + 2 * k], acc);
                acc = fmaf(f.y, wd[c + 2 * k + 1], acc);
            }
        }
        out[(size_t)(g0 + g) * NJN + j] = acc;
    }
}

extern "C" void kernel_launch(void* const* d_in, const int* in_sizes, int n_in,
                              void* d_out, int out_size)
{
    const float* obs    = (const float*)d_in[0];
    const float* We_b   = (const float*)d_in[1];
    const float* be_b   = (const float*)d_in[2];
    const float* We_j   = (const float*)d_in[3];
    const float* be_j   = (const float*)d_in[4];
    const float* W_rel  = (const float*)d_in[5];
    const float* W_root = (const float*)d_in[6];
    const float* b_rel  = (const float*)d_in[7];
    const float* W_dec  = (const float*)d_in[8];
    const float* b_dec  = (const float*)d_in[9];
    float*       out    = (float*)d_out;

    const int B = in_sizes[0] / OBS_LEN;

    conv_weights_kernel<<<(NLAYER * 2 * H * H + 255) / 256, 256>>>(W_rel, W_root);

    const int ntiles = (B + GPT - 1) / GPT;
    cudaFuncSetAttribute(gnn_mma_kernel,
                         cudaFuncAttributeMaxDynamicSharedMemorySize, (int)SMEM_DYN);
    gnn_mma_kernel<<<ntiles, NTHREADS, SMEM_DYN>>>(
        obs, We_b, be_b, We_j, be_j, b_rel, W_dec, b_dec, out, B);
}

// round 16
// speedup vs baseline: 1.4472x; 1.4472x over previous
#include <cuda_runtime.h>
#include <cuda_fp16.h>
#include <stdint.h>
#include <math.h>

namespace {
constexpr int H = 128, NNODE = 13, NJN = 12, OBS_LEN = 141, NLAYER = 3;
constexpr int GPT = 9;               // graphs per CTA -> 117 rows, padded to 128
constexpr int MROWS = 128;
constexpr int NTHREADS = 1024;       // 32 warps: 4 M-slices x 8 N-slices
constexpr int BASE_F = 33, JOINT_F = 9;

constexpr uint32_t PITCHB = 272;     // fp16 row: 128 elems + 8 pad (conflict-free ld/stmatrix)
constexpr uint32_t MATB   = MROWS * PITCHB;        // 34816

constexpr uint32_t OFF_XH  = 0;              // X fp16 (all layers; decoder reads fp16)
constexpr uint32_t OFF_Z1  = MATB;           // Z1 fp16 (single plane)
constexpr uint32_t OFF_Z2  = 2 * MATB;       // Z2 fp16 (bias folded in)
constexpr uint32_t OFF_W1  = 3 * MATB;       // W_rel fp16
constexpr uint32_t OFF_W2  = 4 * MATB;       // W_root fp16
constexpr uint32_t OFF_OBS = 5 * MATB;
constexpr uint32_t OFF_BIAS = OFF_OBS + GPT * 144 * 4;
constexpr uint32_t BO_BEB = 0, BO_BEJ = 512, BO_BREL = 1024, BO_WDEC = 2560, BO_BDEC = 3072;
constexpr uint32_t OFF_WEB = OFF_Z1;         // encoder weights (pre-layer0, in Z1 area)
constexpr uint32_t OFF_WEJ = OFF_Z1 + 16896;
constexpr uint32_t SMEM_DYN = OFF_BIAS + 3104;     // ~178.1 KB

__device__ __constant__ int8_t NSRC[13] = {4,2,2,1,2,2,1,2,2,1,2,2,1};
__device__ __constant__ int8_t SRCS[13][4] = {
    {1,4,7,10},{0,2,0,0},{1,3,0,0},{2,0,0,0},{0,5,0,0},{4,6,0,0},{5,0,0,0},
    {0,8,0,0},{7,9,0,0},{8,0,0,0},{0,11,0,0},{10,12,0,0},{11,0,0,0}};
__device__ __constant__ int8_t BIDX[11] = {0,1,2,3,4,5,6,7,8,45,46};

__device__ __half g_wh[NLAYER][2][H * H];    // fp16 weights [layer][rel/root][n*128+k]

__device__ __forceinline__ uint32_t smem_u32(const void* p) {
    uint32_t a;
    asm("{ .reg .u64 t; cvta.to.shared.u64 t, %1; cvt.u32.u64 %0, t; }" : "=r"(a) : "l"(p));
    return a;
}
__device__ __forceinline__ float elu1(float v) { return v > 0.f ? v : __expf(v) - 1.f; }

__device__ __forceinline__ void ldsm4(uint32_t& r0, uint32_t& r1, uint32_t& r2, uint32_t& r3,
                                      uint32_t addr) {
    asm volatile("ldmatrix.sync.aligned.m8n8.x4.shared.b16 {%0,%1,%2,%3}, [%4];"
                 : "=r"(r0), "=r"(r1), "=r"(r2), "=r"(r3) : "r"(addr));
}
__device__ __forceinline__ void stsm4(uint32_t addr, uint32_t r0, uint32_t r1,
                                      uint32_t r2, uint32_t r3) {
    asm volatile("stmatrix.sync.aligned.m8n8.x4.shared.b16 [%0], {%1,%2,%3,%4};"
                 :: "r"(addr), "r"(r0), "r"(r1), "r"(r2), "r"(r3) : "memory");
}
__device__ __forceinline__ void mma16816(float* c, const uint32_t* a, uint32_t b0, uint32_t b1) {
    asm volatile(
        "mma.sync.aligned.m16n8k16.row.col.f32.f16.f16.f32 "
        "{%0,%1,%2,%3}, {%4,%5,%6,%7}, {%8,%9}, {%0,%1,%2,%3};"
        : "+f"(c[0]), "+f"(c[1]), "+f"(c[2]), "+f"(c[3])
        : "r"(a[0]), "r"(a[1]), "r"(a[2]), "r"(a[3]), "r"(b0), "r"(b1));
}

// packed f32x2 -> f16x2 (low half = first arg; PTX puts first source in HIGH half)
__device__ __forceinline__ uint32_t cvtpack(float lo, float hi) {
    uint32_t r;
    asm("cvt.rn.f16x2.f32 %0, %1, %2;" : "=r"(r) : "f"(hi), "f"(lo));
    return r;
}
__device__ __forceinline__ void store8h(char* sm, uint32_t doff, const float* v) {
    uint4 hh;
    uint32_t* ph = (uint32_t*)&hh;
#pragma unroll
    for (int k = 0; k < 4; k++) ph[k] = cvtpack(v[2 * k], v[2 * k + 1]);
    *(uint4*)(sm + OFF_XH + doff) = hh;
}
// packed half2 add on all 4 words of a uint4
__device__ __forceinline__ void hadd2u4(uint4& s, uint4 p) {
    __half2* a = reinterpret_cast<__half2*>(&s);
    const __half2* b = reinterpret_cast<const __half2*>(&p);
#pragma unroll
    for (int k = 0; k < 4; k++) a[k] = __hadd2(a[k], b[k]);
}
} // namespace

__global__ void conv_weights_kernel(const float* __restrict__ W_rel,
                                    const float* __restrict__ W_root) {
    int i = blockIdx.x * blockDim.x + threadIdx.x;
    if (i >= NLAYER * 2 * H * H) return;
    int l = i / (2 * H * H);
    int r = i % (2 * H * H);
    int g = r / (H * H);
    int e = r % (H * H);
    float w = (g == 0) ? W_rel[l * H * H + e] : W_root[l * H * H + e];
    g_wh[l][g][e] = __float2half_rn(w);
}

__global__ __launch_bounds__(NTHREADS, 1) void gnn_mma_kernel(
    const float* __restrict__ obs,
    const float* __restrict__ We_b, const float* __restrict__ be_b,
    const float* __restrict__ We_j, const float* __restrict__ be_j,
    const float* __restrict__ b_rel,
    const float* __restrict__ W_dec, const float* __restrict__ b_dec,
    float* __restrict__ out, int B)
{
    extern __shared__ char sm[];
    const uint32_t sb = smem_u32(sm);
    const int tid = threadIdx.x, lane = tid & 31, wid = tid >> 5;
    const int m0 = (wid >> 3) * 32;          // 32-row slice (4 slices)
    const int n0 = (wid & 7) * 16;           // 16-col slice (8 slices)
    const int g0 = blockIdx.x * GPT;
    const int ng = min(GPT, B - g0);
    const int rows_real = ng * NNODE;

    // ---- stage biases / encoder weights / obs ----
    if (tid < H) {
        ((float*)(sm + OFF_BIAS + BO_BEB))[tid]  = be_b[tid];
        ((float*)(sm + OFF_BIAS + BO_BEJ))[tid]  = be_j[tid];
        ((float*)(sm + OFF_BIAS + BO_WDEC))[tid] = W_dec[tid];
    }
    if (tid >= H && tid < H + NLAYER * H)
        ((float*)(sm + OFF_BIAS + BO_BREL))[tid - H] = b_rel[tid - H];
    if (tid == 0) ((float*)(sm + OFF_BIAS + BO_BDEC))[0] = b_dec[0];
    for (int i = tid; i < H * BASE_F; i += NTHREADS) {
        int h = i / BASE_F, f = i - h * BASE_F;
        ((float*)(sm + OFF_WEB))[f * H + h] = We_b[i];
    }
    for (int i = tid; i < H * JOINT_F; i += NTHREADS) {
        int h = i / JOINT_F, f = i - h * JOINT_F;
        ((float*)(sm + OFF_WEJ))[f * H + h] = We_j[i];
    }
    for (int i = tid; i < ng * OBS_LEN; i += NTHREADS) {
        int g = i / OBS_LEN, k = i - g * OBS_LEN;
        ((float*)(sm + OFF_OBS))[g * 144 + k] = obs[(size_t)(g0 + g) * OBS_LEN + k];
    }
    __syncthreads();

    // ---- phase A: encoder (X fp16) + stage W(0) concurrently ----
    {
        const uint4* rel = (const uint4*)&g_wh[0][0][0];
        const uint4* roo = (const uint4*)&g_wh[0][1][0];
        for (int idx = tid; idx < H * 16; idx += NTHREADS) {
            uint32_t d = (uint32_t)(idx >> 4) * PITCHB + (uint32_t)(idx & 15) * 16;
            *(uint4*)(sm + OFF_W1 + d) = rel[idx];
            *(uint4*)(sm + OFF_W2 + d) = roo[idx];
        }
    }
    for (int idx = tid; idx < MROWS * 16; idx += NTHREADS) {
        int row = idx >> 4, c0 = (idx & 15) << 3;
        uint32_t doff = (uint32_t)row * PITCHB + (uint32_t)c0 * 2;
        if (row >= rows_real) {
            *(uint4*)(sm + OFF_XH + doff) = make_uint4(0, 0, 0, 0);  // zero pads ONCE
            continue;
        }
        int g = row / NNODE, n = row - g * NNODE;
        const float* ob = (const float*)(sm + OFF_OBS) + g * 144;
        float acc[8];
        if (n == 0) {
            const float* be = (const float*)(sm + OFF_BIAS + BO_BEB);
#pragma unroll
            for (int e = 0; e < 8; e++) acc[e] = be[c0 + e];
#pragma unroll
            for (int t = 0; t < 3; t++)
#pragma unroll
                for (int i2 = 0; i2 < 11; i2++) {
                    float ft = ob[t * 47 + BIDX[i2]];
                    const float* w = (const float*)(sm + OFF_WEB) + (t * 11 + i2) * H + c0;
#pragma unroll
                    for (int e = 0; e < 8; e++) acc[e] = fmaf(ft, w[e], acc[e]);
                }
        } else {
            int j = n - 1;
            const float* be = (const float*)(sm + OFF_BIAS + BO_BEJ);
#pragma unroll
            for (int e = 0; e < 8; e++) acc[e] = be[c0 + e];
#pragma unroll
            for (int f = 0; f < 9; f++) {
                float ft = ob[(f / 3) * 47 + 9 + (f % 3) * 12 + j];
                const float* w = (const float*)(sm + OFF_WEJ) + f * H + c0;
#pragma unroll
                for (int e = 0; e < 8; e++) acc[e] = fmaf(ft, w[e], acc[e]);
            }
        }
#pragma unroll
        for (int e = 0; e < 8; e++) acc[e] = elu1(acc[e]);
        store8h(sm, doff, acc);
    }

    // ---- layers:  x' = elu( S·(X@Wrel^T) + X@Wroot^T + b ) ----
    const int cb = n0 + 2 * (lane & 3);      // fragment col base for this thread
    for (int l = 0; l < NLAYER; l++) {
        __syncthreads();  // X(l)+W(l) ready; prev pass's Z reads done

        // acc1 = X@W1^T; acc2 = bias + X@W2^T (bias folded -> Z2 carries it)
        float acc1[2][2][4], acc2[2][2][4];   // [mt][ns][4]
        {
            const float* brl = (const float*)(sm + OFF_BIAS + BO_BREL) + l * H;
#pragma unroll
            for (int mt = 0; mt < 2; mt++)
#pragma unroll
                for (int ns = 0; ns < 2; ns++) {
                    const float b0 = brl[cb + ns * 8];
                    const float b1 = brl[cb + ns * 8 + 1];
                    acc1[mt][ns][0] = 0.f; acc1[mt][ns][1] = 0.f;
                    acc1[mt][ns][2] = 0.f; acc1[mt][ns][3] = 0.f;
                    acc2[mt][ns][0] = b0;  acc2[mt][ns][1] = b1;
                    acc2[mt][ns][2] = b0;  acc2[mt][ns][3] = b1;
                }
        }
        {
            const uint32_t arow = (uint32_t)(lane & 15);
            const uint32_t acol = (uint32_t)((lane >> 4) << 4);
            const uint32_t brow = (uint32_t)((lane & 7) + ((lane >> 4) << 3));
            const uint32_t bcol = (uint32_t)(((lane >> 3) & 1) << 4);
            const uint32_t aH0 = sb + OFF_XH + ((uint32_t)m0 + arow) * PITCHB + acol;
            const uint32_t bro = ((uint32_t)n0 + brow) * PITCHB + bcol;
            const uint32_t b10 = sb + OFF_W1 + bro;
            const uint32_t b20 = sb + OFF_W2 + bro;
#pragma unroll 2
            for (int k = 0; k < 8; k++) {
                const uint32_t kb = (uint32_t)k * 32u;
                uint32_t ah[2][4];
                ldsm4(ah[0][0], ah[0][1], ah[0][2], ah[0][3], aH0 + kb);
                ldsm4(ah[1][0], ah[1][1], ah[1][2], ah[1][3], aH0 + 16u * PITCHB + kb);
                uint32_t w0, w1, w2, w3;
                ldsm4(w0, w1, w2, w3, b10 + kb);
#pragma unroll
                for (int mt = 0; mt < 2; mt++) {
                    mma16816(acc1[mt][0], ah[mt], w0, w1);
                    mma16816(acc1[mt][1], ah[mt], w2, w3);
                }
                ldsm4(w0, w1, w2, w3, b20 + kb);
#pragma unroll
                for (int mt = 0; mt < 2; mt++) {
                    mma16816(acc2[mt][0], ah[mt], w0, w1);
                    mma16816(acc2[mt][1], ah[mt], w2, w3);
                }
            }
        }

        // coalesced spill via stmatrix: Z1 fp16, Z2 fp16 (bias included)
        {
            const uint32_t t = (uint32_t)lane >> 3;          // tile 0..3
            const uint32_t srow = (uint32_t)m0 + ((t >> 1) << 3) + (lane & 7);
            const uint32_t scol = (uint32_t)n0 + (t & 1) * 8;
            const uint32_t boff = srow * PITCHB + scol * 2;
#pragma unroll
            for (int mt = 0; mt < 2; mt++) {
                const uint32_t off = boff + (uint32_t)mt * (16u * PITCHB);
                // reg r for tile t: t0=(half0,ns0) t1=(half0,ns1) t2=(half1,ns0) t3=(half1,ns1)
                stsm4(sb + OFF_Z1 + off,
                      cvtpack(acc1[mt][0][0], acc1[mt][0][1]),
                      cvtpack(acc1[mt][1][0], acc1[mt][1][1]),
                      cvtpack(acc1[mt][0][2], acc1[mt][0][3]),
                      cvtpack(acc1[mt][1][2], acc1[mt][1][3]));
                stsm4(sb + OFF_Z2 + off,
                      cvtpack(acc2[mt][0][0], acc2[mt][0][1]),
                      cvtpack(acc2[mt][1][0], acc2[mt][1][1]),
                      cvtpack(acc2[mt][0][2], acc2[mt][0][3]),
                      cvtpack(acc2[mt][1][2], acc2[mt][1][3]));
            }
        }
        __syncthreads();  // Z complete; all GEMM X reads done -> XH writable

        // coalesced row-major epilogue: x' = elu( Z2 + S·Z1 ) -> X fp16
        // accumulation in packed half2 (HADD2); final ELU in fp32
        for (int idx = tid; idx < MROWS * 16; idx += NTHREADS) {
            int row = idx >> 4, c0 = (idx & 15) << 3;
            if (row >= rows_real) continue;     // pads stay zero from encoder
            uint32_t doff = (uint32_t)row * PITCHB + (uint32_t)c0 * 2;
            uint4 s = *(const uint4*)(sm + OFF_Z2 + doff);
            const int gb = (row / NNODE) * NNODE;
            const int n  = row - gb;
            const int cnt = NSRC[n];
            for (int k2 = 0; k2 < cnt; k2++) {
                uint32_t soff = (uint32_t)(gb + SRCS[n][k2]) * PITCHB + (uint32_t)c0 * 2;
                hadd2u4(s, *(const uint4*)(sm + OFF_Z1 + soff));
            }
            float v[8];
            const uint32_t* w32 = (const uint32_t*)&s;
#pragma unroll
            for (int k = 0; k < 4; k++) {
                float2 f = __half22float2(*reinterpret_cast<const __half2*>(&w32[k]));
                v[2 * k]     = elu1(f.x);
                v[2 * k + 1] = elu1(f.y);
            }
            store8h(sm, doff, v);
        }

        // stage W(l+1) in the same phase (W buffers idle during pass)
        if (l + 1 < NLAYER) {
            const uint4* rel = (const uint4*)&g_wh[l + 1][0][0];
            const uint4* roo = (const uint4*)&g_wh[l + 1][1][0];
            for (int idx = tid; idx < H * 16; idx += NTHREADS) {
                uint32_t d = (uint32_t)(idx >> 4) * PITCHB + (uint32_t)(idx & 15) * 16;
                *(uint4*)(sm + OFF_W1 + d) = rel[idx];
                *(uint4*)(sm + OFF_W2 + d) = roo[idx];
            }
        }
    }
    __syncthreads();

    // ---- decoder (final X fp16 at OFF_XH) ----
    if (tid < ng * NJN) {
        int g = tid / NJN, j = tid - g * NJN;
        const char* xrow = sm + OFF_XH + (uint32_t)(g * NNODE + 1 + j) * PITCHB;
        const float* wd = (const float*)(sm + OFF_BIAS + BO_WDEC);
        float acc = ((const float*)(sm + OFF_BIAS + BO_BDEC))[0];
#pragma unroll
        for (int c = 0; c < H; c += 8) {
            uint4 p = *(const uint4*)(xrow + c * 2);
            const uint32_t* w32 = (const uint32_t*)&p;
#pragma unroll
            for (int k = 0; k < 4; k++) {
                float2 f = __half22float2(*reinterpret_cast<const __half2*>(&w32[k]));
                acc = fmaf(f.x, wd[c + 2 * k], acc);
                acc = fmaf(f.y, wd[c + 2 * k + 1], acc);
            }
        }
        out[(size_t)(g0 + g) * NJN + j] = acc;
    }
}

extern "C" void kernel_launch(void* const* d_in, const int* in_sizes, int n_in,
                              void* d_out, int out_size)
{
    const float* obs    = (const float*)d_in[0];
    const float* We_b   = (const float*)d_in[1];
    const float* be_b   = (const float*)d_in[2];
    const float* We_j   = (const float*)d_in[3];
    const float* be_j   = (const float*)d_in[4];
    const float* W_rel  = (const float*)d_in[5];
    const float* W_root = (const float*)d_in[6];
    const float* b_rel  = (const float*)d_in[7];
    const float* W_dec  = (const float*)d_in[8];
    const float* b_dec  = (const float*)d_in[9];
    float*       out    = (float*)d_out;

    const int B = in_sizes[0] / OBS_LEN;

    conv_weights_kernel<<<(NLAYER * 2 * H * H + 255) / 256, 256>>>(W_rel, W_root);

    const int ntiles = (B + GPT - 1) / GPT;
    cudaFuncSetAttribute(gnn_mma_kernel,
                         cudaFuncAttributeMaxDynamicSharedMemorySize, (int)SMEM_DYN);
    gnn_mma_kernel<<<ntiles, NTHREADS, SMEM_DYN>>>(
        obs, We_b, be_b, We_j, be_j, b_rel, W_dec, b_dec, out, B);
}

// round 17
// speedup vs baseline: 1.4546x; 1.0051x over previous
#include <cuda_runtime.h>
#include <cuda_fp16.h>
#include <stdint.h>
#include <math.h>

namespace {
constexpr int H = 128, NNODE = 13, NJN = 12, OBS_LEN = 141, NLAYER = 3;
constexpr int GPT = 9;               // graphs per CTA -> 117 rows, padded to 128
constexpr int MROWS = 128;
constexpr int NTHREADS = 1024;       // 32 warps: 4 M-slices x 8 N-slices
constexpr int BASE_F = 33, JOINT_F = 9;

constexpr uint32_t PITCHB = 272;     // fp16 row: 128 elems + 8 pad (conflict-free ld/stmatrix)
constexpr uint32_t MATB   = MROWS * PITCHB;        // 34816

constexpr uint32_t OFF_XH  = 0;              // X fp16 (all layers; decoder reads fp16)
constexpr uint32_t OFF_Z1  = MATB;           // Z1 fp16
constexpr uint32_t OFF_Z2  = 2 * MATB;       // Z2 fp16 (bias folded in)
constexpr uint32_t OFF_OBS = 3 * MATB;
constexpr uint32_t OFF_BIAS = OFF_OBS + GPT * 144 * 4;
constexpr uint32_t BO_BEB = 0, BO_BEJ = 512, BO_BREL = 1024, BO_WDEC = 2560, BO_BDEC = 3072;
constexpr uint32_t OFF_WEB = OFF_Z1;         // encoder weights (pre-layer0, in Z1 area)
constexpr uint32_t OFF_WEJ = OFF_Z1 + 16896;
constexpr uint32_t SMEM_DYN = OFF_BIAS + 3104;     // ~110.1 KB -> big L1D carveout for W

__device__ __constant__ int8_t NSRC[13] = {4,2,2,1,2,2,1,2,2,1,2,2,1};
__device__ __constant__ int8_t SRCS[13][4] = {
    {1,4,7,10},{0,2,0,0},{1,3,0,0},{2,0,0,0},{0,5,0,0},{4,6,0,0},{5,0,0,0},
    {0,8,0,0},{7,9,0,0},{8,0,0,0},{0,11,0,0},{10,12,0,0},{11,0,0,0}};
__device__ __constant__ int8_t BIDX[11] = {0,1,2,3,4,5,6,7,8,45,46};

// W prepacked into mma B-fragment order:
// index = (((l*2+grp)*8 + nslice)*8 + kchunk)*32 + lane ; uint4 = {w0,w1,w2,w3}
// thread t of a warp on n-slice ns, k-chunk kb needs:
//   w0 = {W[n0+t/4][kb+2(t%4)],   W[n0+t/4][kb+2(t%4)+1]}
//   w1 = same k+8 ; w2 = n+8 ; w3 = n+8, k+8      (B[k][n] = W[n][k])
__device__ uint4 g_wfrag[NLAYER * 2 * 8 * 8 * 32];

__device__ __forceinline__ uint32_t smem_u32(const void* p) {
    uint32_t a;
    asm("{ .reg .u64 t; cvta.to.shared.u64 t, %1; cvt.u32.u64 %0, t; }" : "=r"(a) : "l"(p));
    return a;
}
__device__ __forceinline__ float elu1(float v) { return v > 0.f ? v : __expf(v) - 1.f; }

__device__ __forceinline__ void ldsm4(uint32_t& r0, uint32_t& r1, uint32_t& r2, uint32_t& r3,
                                      uint32_t addr) {
    asm volatile("ldmatrix.sync.aligned.m8n8.x4.shared.b16 {%0,%1,%2,%3}, [%4];"
                 : "=r"(r0), "=r"(r1), "=r"(r2), "=r"(r3) : "r"(addr));
}
__device__ __forceinline__ void stsm4(uint32_t addr, uint32_t r0, uint32_t r1,
                                      uint32_t r2, uint32_t r3) {
    asm volatile("stmatrix.sync.aligned.m8n8.x4.shared.b16 [%0], {%1,%2,%3,%4};"
                 :: "r"(addr), "r"(r0), "r"(r1), "r"(r2), "r"(r3) : "memory");
}
__device__ __forceinline__ void mma16816(float* c, const uint32_t* a, uint32_t b0, uint32_t b1) {
    asm volatile(
        "mma.sync.aligned.m16n8k16.row.col.f32.f16.f16.f32 "
        "{%0,%1,%2,%3}, {%4,%5,%6,%7}, {%8,%9}, {%0,%1,%2,%3};"
        : "+f"(c[0]), "+f"(c[1]), "+f"(c[2]), "+f"(c[3])
        : "r"(a[0]), "r"(a[1]), "r"(a[2]), "r"(a[3]), "r"(b0), "r"(b1));
}

// packed f32x2 -> f16x2 (low half = first arg; PTX puts first source in HIGH half)
__device__ __forceinline__ uint32_t cvtpack(float lo, float hi) {
    uint32_t r;
    asm("cvt.rn.f16x2.f32 %0, %1, %2;" : "=r"(r) : "f"(hi), "f"(lo));
    return r;
}
__device__ __forceinline__ void store8h(char* sm, uint32_t doff, const float* v) {
    uint4 hh;
    uint32_t* ph = (uint32_t*)&hh;
#pragma unroll
    for (int k = 0; k < 4; k++) ph[k] = cvtpack(v[2 * k], v[2 * k + 1]);
    *(uint4*)(sm + OFF_XH + doff) = hh;
}
// packed half2 add on all 4 words of a uint4
__device__ __forceinline__ void hadd2u4(uint4& s, uint4 p) {
    __half2* a = reinterpret_cast<__half2*>(&s);
    const __half2* b = reinterpret_cast<const __half2*>(&p);
#pragma unroll
    for (int k = 0; k < 4; k++) a[k] = __hadd2(a[k], b[k]);
}
} // namespace

__global__ void pack_w_kernel(const float* __restrict__ W_rel,
                              const float* __restrict__ W_root) {
    int i = blockIdx.x * blockDim.x + threadIdx.x;
    if (i >= NLAYER * 2 * 8 * 8 * 32) return;
    int lane = i & 31;
    int kc8  = (i >> 5) & 7;
    int ns   = (i >> 8) & 7;
    int grp  = (i >> 11) & 1;
    int l    = i >> 12;
    const float* W = ((grp == 0) ? W_rel : W_root) + l * H * H;
    int nr = ns * 16 + (lane >> 2);
    int kc = kc8 * 16 + (lane & 3) * 2;
    uint4 r;
    r.x = cvtpack(W[nr * H + kc],           W[nr * H + kc + 1]);
    r.y = cvtpack(W[nr * H + kc + 8],       W[nr * H + kc + 9]);
    r.z = cvtpack(W[(nr + 8) * H + kc],     W[(nr + 8) * H + kc + 1]);
    r.w = cvtpack(W[(nr + 8) * H + kc + 8], W[(nr + 8) * H + kc + 9]);
    g_wfrag[i] = r;
}

__global__ __launch_bounds__(NTHREADS, 1) void gnn_mma_kernel(
    const float* __restrict__ obs,
    const float* __restrict__ We_b, const float* __restrict__ be_b,
    const float* __restrict__ We_j, const float* __restrict__ be_j,
    const float* __restrict__ b_rel,
    const float* __restrict__ W_dec, const float* __restrict__ b_dec,
    float* __restrict__ out, int B)
{
    extern __shared__ char sm[];
    const uint32_t sb = smem_u32(sm);
    const int tid = threadIdx.x, lane = tid & 31, wid = tid >> 5;
    const int m0 = (wid >> 3) * 32;          // 32-row slice (4 slices)
    const int n0 = (wid & 7) * 16;           // 16-col slice (8 slices)
    const int g0 = blockIdx.x * GPT;
    const int ng = min(GPT, B - g0);
    const int rows_real = ng * NNODE;

    // ---- stage biases / encoder weights / obs ----
    if (tid < H) {
        ((float*)(sm + OFF_BIAS + BO_BEB))[tid]  = be_b[tid];
        ((float*)(sm + OFF_BIAS + BO_BEJ))[tid]  = be_j[tid];
        ((float*)(sm + OFF_BIAS + BO_WDEC))[tid] = W_dec[tid];
    }
    if (tid >= H && tid < H + NLAYER * H)
        ((float*)(sm + OFF_BIAS + BO_BREL))[tid - H] = b_rel[tid - H];
    if (tid == 0) ((float*)(sm + OFF_BIAS + BO_BDEC))[0] = b_dec[0];
    for (int i = tid; i < H * BASE_F; i += NTHREADS) {
        int h = i / BASE_F, f = i - h * BASE_F;
        ((float*)(sm + OFF_WEB))[f * H + h] = We_b[i];
    }
    for (int i = tid; i < H * JOINT_F; i += NTHREADS) {
        int h = i / JOINT_F, f = i - h * JOINT_F;
        ((float*)(sm + OFF_WEJ))[f * H + h] = We_j[i];
    }
    for (int i = tid; i < ng * OBS_LEN; i += NTHREADS) {
        int g = i / OBS_LEN, k = i - g * OBS_LEN;
        ((float*)(sm + OFF_OBS))[g * 144 + k] = obs[(size_t)(g0 + g) * OBS_LEN + k];
    }
    __syncthreads();

    // ---- encoder (X fp16) ----
    for (int idx = tid; idx < MROWS * 16; idx += NTHREADS) {
        int row = idx >> 4, c0 = (idx & 15) << 3;
        uint32_t doff = (uint32_t)row * PITCHB + (uint32_t)c0 * 2;
        if (row >= rows_real) {
            *(uint4*)(sm + OFF_XH + doff) = make_uint4(0, 0, 0, 0);  // zero pads ONCE
            continue;
        }
        int g = row / NNODE, n = row - g * NNODE;
        const float* ob = (const float*)(sm + OFF_OBS) + g * 144;
        float acc[8];
        if (n == 0) {
            const float* be = (const float*)(sm + OFF_BIAS + BO_BEB);
#pragma unroll
            for (int e = 0; e < 8; e++) acc[e] = be[c0 + e];
#pragma unroll
            for (int t = 0; t < 3; t++)
#pragma unroll
                for (int i2 = 0; i2 < 11; i2++) {
                    float ft = ob[t * 47 + BIDX[i2]];
                    const float* w = (const float*)(sm + OFF_WEB) + (t * 11 + i2) * H + c0;
#pragma unroll
                    for (int e = 0; e < 8; e++) acc[e] = fmaf(ft, w[e], acc[e]);
                }
        } else {
            int j = n - 1;
            const float* be = (const float*)(sm + OFF_BIAS + BO_BEJ);
#pragma unroll
            for (int e = 0; e < 8; e++) acc[e] = be[c0 + e];
#pragma unroll
            for (int f = 0; f < 9; f++) {
                float ft = ob[(f / 3) * 47 + 9 + (f % 3) * 12 + j];
                const float* w = (const float*)(sm + OFF_WEJ) + f * H + c0;
#pragma unroll
                for (int e = 0; e < 8; e++) acc[e] = fmaf(ft, w[e], acc[e]);
            }
        }
#pragma unroll
        for (int e = 0; e < 8; e++) acc[e] = elu1(acc[e]);
        store8h(sm, doff, acc);
    }

    // ---- layers:  x' = elu( S·(X@Wrel^T) + X@Wroot^T + b ) ----
    const int cb = n0 + 2 * (lane & 3);      // fragment col base for this thread
    for (int l = 0; l < NLAYER; l++) {
        __syncthreads();  // X(l) ready; prev pass's Z reads done

        // acc1 = X@W1^T; acc2 = bias + X@W2^T (bias folded -> Z2 carries it)
        float acc1[2][2][4], acc2[2][2][4];   // [mt][ns][4]
        {
            const float* brl = (const float*)(sm + OFF_BIAS + BO_BREL) + l * H;
#pragma unroll
            for (int mt = 0; mt < 2; mt++)
#pragma unroll
                for (int ns = 0; ns < 2; ns++) {
                    const float b0 = brl[cb + ns * 8];
                    const float b1 = brl[cb + ns * 8 + 1];
                    acc1[mt][ns][0] = 0.f; acc1[mt][ns][1] = 0.f;
                    acc1[mt][ns][2] = 0.f; acc1[mt][ns][3] = 0.f;
                    acc2[mt][ns][0] = b0;  acc2[mt][ns][1] = b1;
                    acc2[mt][ns][2] = b0;  acc2[mt][ns][3] = b1;
                }
        }
        {
            const uint32_t arow = (uint32_t)(lane & 15);
            const uint32_t acol = (uint32_t)((lane >> 4) << 4);
            const uint32_t aH0 = sb + OFF_XH + ((uint32_t)m0 + arow) * PITCHB + acol;
            // fragment-packed W in global (L1/L2-cached; same bytes for all CTAs)
            const uint4* wf1 = g_wfrag + (((l * 2 + 0) * 8 + (wid & 7)) * 8) * 32 + lane;
            const uint4* wf2 = g_wfrag + (((l * 2 + 1) * 8 + (wid & 7)) * 8) * 32 + lane;
#pragma unroll 2
            for (int k = 0; k < 8; k++) {
                const uint32_t kb = (uint32_t)k * 32u;
                uint32_t ah[2][4];
                ldsm4(ah[0][0], ah[0][1], ah[0][2], ah[0][3], aH0 + kb);
                ldsm4(ah[1][0], ah[1][1], ah[1][2], ah[1][3], aH0 + 16u * PITCHB + kb);
                uint4 wa = __ldg(wf1 + k * 32);
#pragma unroll
                for (int mt = 0; mt < 2; mt++) {
                    mma16816(acc1[mt][0], ah[mt], wa.x, wa.y);
                    mma16816(acc1[mt][1], ah[mt], wa.z, wa.w);
                }
                uint4 wb = __ldg(wf2 + k * 32);
#pragma unroll
                for (int mt = 0; mt < 2; mt++) {
                    mma16816(acc2[mt][0], ah[mt], wb.x, wb.y);
                    mma16816(acc2[mt][1], ah[mt], wb.z, wb.w);
                }
            }
        }

        // coalesced spill via stmatrix: Z1 fp16, Z2 fp16 (bias included)
        {
            const uint32_t t = (uint32_t)lane >> 3;          // tile 0..3
            const uint32_t srow = (uint32_t)m0 + ((t >> 1) << 3) + (lane & 7);
            const uint32_t scol = (uint32_t)n0 + (t & 1) * 8;
            const uint32_t boff = srow * PITCHB + scol * 2;
#pragma unroll
            for (int mt = 0; mt < 2; mt++) {
                const uint32_t off = boff + (uint32_t)mt * (16u * PITCHB);
                stsm4(sb + OFF_Z1 + off,
                      cvtpack(acc1[mt][0][0], acc1[mt][0][1]),
                      cvtpack(acc1[mt][1][0], acc1[mt][1][1]),
                      cvtpack(acc1[mt][0][2], acc1[mt][0][3]),
                      cvtpack(acc1[mt][1][2], acc1[mt][1][3]));
                stsm4(sb + OFF_Z2 + off,
                      cvtpack(acc2[mt][0][0], acc2[mt][0][1]),
                      cvtpack(acc2[mt][1][0], acc2[mt][1][1]),
                      cvtpack(acc2[mt][0][2], acc2[mt][0][3]),
                      cvtpack(acc2[mt][1][2], acc2[mt][1][3]));
            }
        }
        __syncthreads();  // Z complete; all GEMM X reads done -> XH writable

        // coalesced row-major epilogue: x' = elu( Z2 + S·Z1 ) -> X fp16
        for (int idx = tid; idx < MROWS * 16; idx += NTHREADS) {
            int row = idx >> 4, c0 = (idx & 15) << 3;
            if (row >= rows_real) continue;     // pads stay zero from encoder
            uint32_t doff = (uint32_t)row * PITCHB + (uint32_t)c0 * 2;
            uint4 s = *(const uint4*)(sm + OFF_Z2 + doff);
            const int gb = (row / NNODE) * NNODE;
            const int n  = row - gb;
            const int cnt = NSRC[n];
            for (int k2 = 0; k2 < cnt; k2++) {
                uint32_t soff = (uint32_t)(gb + SRCS[n][k2]) * PITCHB + (uint32_t)c0 * 2;
                hadd2u4(s, *(const uint4*)(sm + OFF_Z1 + soff));
            }
            float v[8];
            const uint32_t* w32 = (const uint32_t*)&s;
#pragma unroll
            for (int k = 0; k < 4; k++) {
                float2 f = __half22float2(*reinterpret_cast<const __half2*>(&w32[k]));
                v[2 * k]     = elu1(f.x);
                v[2 * k + 1] = elu1(f.y);
            }
            store8h(sm, doff, v);
        }
    }
    __syncthreads();

    // ---- decoder (final X fp16 at OFF_XH) ----
    if (tid < ng * NJN) {
        int g = tid / NJN, j = tid - g * NJN;
        const char* xrow = sm + OFF_XH + (uint32_t)(g * NNODE + 1 + j) * PITCHB;
        const float* wd = (const float*)(sm + OFF_BIAS + BO_WDEC);
        float acc = ((const float*)(sm + OFF_BIAS + BO_BDEC))[0];
#pragma unroll
        for (int c = 0; c < H; c += 8) {
            uint4 p = *(const uint4*)(xrow + c * 2);
            const uint32_t* w32 = (const uint32_t*)&p;
#pragma unroll
            for (int k = 0; k < 4; k++) {
                float2 f = __half22float2(*reinterpret_cast<const __half2*>(&w32[k]));
                acc = fmaf(f.x, wd[c + 2 * k], acc);
                acc = fmaf(f.y, wd[c + 2 * k + 1], acc);
            }
        }
        out[(size_t)(g0 + g) * NJN + j] = acc;
    }
}

extern "C" void kernel_launch(void* const* d_in, const int* in_sizes, int n_in,
                              void* d_out, int out_size)
{
    const float* obs    = (const float*)d_in[0];
    const float* We_b   = (const float*)d_in[1];
    const float* be_b   = (const float*)d_in[2];
    const float* We_j   = (const float*)d_in[3];
    const float* be_j   = (const float*)d_in[4];
    const float* W_rel  = (const float*)d_in[5];
    const float* W_root = (const float*)d_in[6];
    const float* b_rel  = (const float*)d_in[7];
    const float* W_dec  = (const float*)d_in[8];
    const float* b_dec  = (const float*)d_in[9];
    float*       out    = (float*)d_out;

    const int B = in_sizes[0] / OBS_LEN;

    pack_w_kernel<<<(NLAYER * 2 * 8 * 8 * 32 + 255) / 256, 256>>>(W_rel, W_root);

    const int ntiles = (B + GPT - 1) / GPT;
    cudaFuncSetAttribute(gnn_mma_kernel,
                         cudaFuncAttributeMaxDynamicSharedMemorySize, (int)SMEM_DYN);
    gnn_mma_kernel<<<ntiles, NTHREADS, SMEM_DYN>>>(
        obs, We_b, be_b, We_j, be_j, b_rel, W_dec, b_dec, out, B);
}